// round 14
// baseline (speedup 1.0000x reference)
#include <cuda_runtime.h>

#define NBATCH 16
#define NPTS0  4096
#define FULLMASK 0xffffffffu

// ---------------- device scratch (no allocations allowed) ------------------
__device__ float4 g_xyz0[NBATCH * NPTS0];      // x,y,z,|p|^2
__device__ float  g_pts0[NBATCH * NPTS0 * 9];
__device__ float4 g_nx1[NBATCH * 1024];
__device__ float  g_f1 [NBATCH * 1024 * 64];
__device__ float4 g_nx2[NBATCH * 256];
__device__ float  g_f2 [NBATCH * 256 * 128];
__device__ float4 g_nx3[NBATCH * 64];
__device__ float  g_f3 [NBATCH * 64 * 256];
__device__ float4 g_nx4[NBATCH * 16];
__device__ float  g_f4 [NBATCH * 16 * 512];

// ---------------- d_out offsets (float elements) ----------------------------
#define O1 0        // [16,3,4096]
#define O2 196608   // [16,3,1024]
#define O3 245760   // [16,3,256]
#define O4 258048   // [16,3,64]
#define O5 261120   // [16,3,16]
#define O6 261888   // [16,64,1024]
#define O7 1310464  // [16,128,256]
#define O8 1834752  // [16,256,64]
#define O9 2096896  // [16,512,16]

__device__ __forceinline__ float sq3(float a, float b, float c) {
    return __fadd_rn(__fadd_rn(__fmul_rn(a, a), __fmul_rn(b, b)), __fmul_rn(c, c));
}

// ---- packed f32x2 helpers (lanewise rn == __fadd_rn/__fmul_rn, bit-exact) --
__device__ __forceinline__ unsigned long long pk2(float lo, float hi) {
    unsigned long long r;
    asm("mov.b64 %0, {%1, %2};" : "=l"(r) : "f"(lo), "f"(hi));
    return r;
}
__device__ __forceinline__ void upk2(float& lo, float& hi, unsigned long long v) {
    asm("mov.b64 {%0, %1}, %2;" : "=f"(lo), "=f"(hi) : "l"(v));
}
__device__ __forceinline__ unsigned long long add2(unsigned long long a, unsigned long long b) {
    unsigned long long r;
    asm("add.rn.f32x2 %0, %1, %2;" : "=l"(r) : "l"(a), "l"(b));
    return r;
}
__device__ __forceinline__ unsigned long long mul2(unsigned long long a, unsigned long long b) {
    unsigned long long r;
    asm("mul.rn.f32x2 %0, %1, %2;" : "=l"(r) : "l"(a), "l"(b));
    return r;
}
__device__ __forceinline__ unsigned long long umax64(unsigned long long a, unsigned long long b) {
    return a > b ? a : b;
}

// ---------------------------------------------------------------------------
// FPS body (R12-validated): coords packed 2-wide in REGISTERS (f32x2 math,
// lanewise bit-exact rn; association (dx^2+dy^2)+dz^2 identical to sq3).
// float4 smem mirror for far-point lookup. Strict ">" argmax over ascending
// p == first-max (jnp semantics); cross-warp tie-break via redux.min.
// STRIDED=true: load coords from raw [9,N]-strided input (x=+0,y=+N,z=+2N),
// w computed as sq3 (bit-identical to the transpose path).
// ---------------------------------------------------------------------------
template <int NPf, int Sf, int NW, bool STRIDED>
__device__ void fps_body(const void* __restrict__ srcv, float4* __restrict__ nx,
                         float* __restrict__ dout, int b, int tid, float4* sc4) {
    constexpr int T = NW * 32;
    constexpr int PPT = (NPf + T - 1) / T;
    constexpr bool GUARD = (NPf % T) != 0;
    constexpr int NPAIR = GUARD ? 0 : (PPT / 2);
    __shared__ unsigned long long skey[2][NW];
    int lane = tid & 31, wd = tid >> 5;

    float tx[PPT], ty[PPT], tz[PPT], dist[PPT];
#pragma unroll
    for (int j = 0; j < PPT; j++) {
        int p = tid + j * T;
        dist[j] = 1e10f;
        tx[j] = 0.f; ty[j] = 0.f; tz[j] = 0.f;
        if (!GUARD || p < NPf) {
            float4 v;
            if constexpr (STRIDED) {
                const float* xin = (const float*)srcv + (size_t)b * 9 * NPf;
                float x = xin[p], y = xin[NPf + p], z = xin[2 * NPf + p];
                v = make_float4(x, y, z, sq3(x, y, z));
            } else {
                v = ((const float4*)srcv)[(size_t)b * NPf + p];
            }
            sc4[p] = v;
            tx[j] = v.x; ty[j] = v.y; tz[j] = v.z;
        }
    }
    unsigned long long CX[NPAIR > 0 ? NPAIR : 1];
    unsigned long long CY[NPAIR > 0 ? NPAIR : 1];
    unsigned long long CZ[NPAIR > 0 ? NPAIR : 1];
#pragma unroll
    for (int g = 0; g < NPAIR; g++) {
        CX[g] = pk2(tx[2 * g], tx[2 * g + 1]);
        CY[g] = pk2(ty[2 * g], ty[2 * g + 1]);
        CZ[g] = pk2(tz[2 * g], tz[2 * g + 1]);
    }
    __syncthreads();

    int far = 0;
    for (int s = 0; s < Sf; s++) {
        float4 f = sc4[far];
        if (tid == 0) {
            nx[(size_t)b * Sf + s] = f;
            dout[((size_t)b * 3 + 0) * Sf + s] = f.x;
            dout[((size_t)b * 3 + 1) * Sf + s] = f.y;
            dout[((size_t)b * 3 + 2) * Sf + s] = f.z;
        }
        unsigned bb = 0u, bi = 0xffffffffu;
        unsigned long long nfx = pk2(-f.x, -f.x);
        unsigned long long nfy = pk2(-f.y, -f.y);
        unsigned long long nfz = pk2(-f.z, -f.z);
#pragma unroll
        for (int g = 0; g < NPAIR; g++) {
            unsigned long long dx = add2(CX[g], nfx);
            unsigned long long dy = add2(CY[g], nfy);
            unsigned long long dz = add2(CZ[g], nfz);
            unsigned long long ss = add2(add2(mul2(dx, dx), mul2(dy, dy)), mul2(dz, dz));
            float d0, d1; upk2(d0, d1, ss);
            int p0 = tid + (2 * g) * T, p1 = p0 + T;
            float n0 = fminf(dist[2 * g], d0);     dist[2 * g] = n0;
            float n1 = fminf(dist[2 * g + 1], d1); dist[2 * g + 1] = n1;
            unsigned u0 = __float_as_uint(n0), u1 = __float_as_uint(n1);
            if (u0 > bb) { bb = u0; bi = (unsigned)p0; }   // strict > over ascending p
            if (u1 > bb) { bb = u1; bi = (unsigned)p1; }   //  == first-max semantics
        }
#pragma unroll
        for (int j = 2 * NPAIR; j < PPT; j++) {   // scalar remainder (guarded)
            int p = tid + j * T;
            if (!GUARD || p < NPf) {
                float dxs = __fadd_rn(tx[j], -f.x);
                float dys = __fadd_rn(ty[j], -f.y);
                float dzs = __fadd_rn(tz[j], -f.z);
                float d = sq3(dxs, dys, dzs);
                float nd = fminf(dist[j], d);
                dist[j] = nd;
                unsigned ub = __float_as_uint(nd);
                if (ub > bb) { bb = ub; bi = (unsigned)p; }
            }
        }
        unsigned mb = __reduce_max_sync(FULLMASK, bb);
        unsigned cand = (bb == mb) ? bi : 0xffffffffu;
        unsigned mi = __reduce_min_sync(FULLMASK, cand);
        if (lane == 0)
            skey[s & 1][wd] = ((unsigned long long)mb << 32) |
                              (unsigned long long)(0xffffffffu - mi);
        __syncthreads();
        unsigned long long kk[NW];
#pragma unroll
        for (int i = 0; i < NW; i++) kk[i] = skey[s & 1][i];
#pragma unroll
        for (int st = NW / 2; st > 0; st >>= 1)
#pragma unroll
            for (int i = 0; i < st; i++) kk[i] = umax64(kk[i], kk[i + st]);
        far = (int)(0xffffffffu - (unsigned)(kk[0] & 0xffffffffu));
    }
}

// ---------------------------------------------------------------------------
// Fused transpose + fps1: blocks [0,16) run fps1 reading the RAW strided
// input (no dependence on the transpose); blocks [16,...) transpose
// [B,9,N] -> point-major scratch (+ |p|^2) and emit output region 1.
// ---------------------------------------------------------------------------
__global__ __launch_bounds__(512) void k_front(const float* __restrict__ in,
                                               float* __restrict__ out1,
                                               float4* __restrict__ nx1,
                                               float* __restrict__ dout2) {
    extern __shared__ float smdyn[];
    int bid = blockIdx.x;
    if (bid < NBATCH) {
        fps_body<4096, 1024, 16, true>(in, nx1, dout2, bid, threadIdx.x,
                                       (float4*)smdyn);
        return;
    }
    int i = (bid - NBATCH) * 512 + threadIdx.x;
    if (i >= NBATCH * NPTS0) return;
    int b = i >> 12;
    int n = i & (NPTS0 - 1);
    const float* src = in + (size_t)b * 9 * NPTS0;
    float v[9];
#pragma unroll
    for (int c = 0; c < 9; c++) v[c] = src[c * NPTS0 + n];
#pragma unroll
    for (int c = 0; c < 9; c++) g_pts0[(size_t)i * 9 + c] = v[c];
    g_xyz0[i] = make_float4(v[0], v[1], v[2], sq3(v[0], v[1], v[2]));
#pragma unroll
    for (int c = 0; c < 3; c++) out1[((size_t)b * 3 + c) * NPTS0 + n] = v[c];
}

// ---------------------------------------------------------------------------
// MLP stage (middle), NC centers register-blocked; OB = CO/8 outputs/thread.
// Weights staged in smem chunks of 16 ci-cols (pitch 20).
// ---------------------------------------------------------------------------
template <int CIa, int CIp, int CO, int PI, int PO, int NC>
__device__ __forceinline__ void mlp_mid(const float* __restrict__ fin,
                                        float* __restrict__ fo,
                                        float* __restrict__ wsm,
                                        const float* __restrict__ W,
                                        const float* __restrict__ Bv, int tid) {
    constexpr int OB = CO / 8;
    int lane = tid & 31;
    int obase = (tid >> 5) * OB;
    float acc[NC][OB];
#pragma unroll
    for (int c = 0; c < NC; c++)
#pragma unroll
        for (int j = 0; j < OB; j++) acc[c][j] = __ldg(Bv + obase + j);
    const float* frow[NC];
#pragma unroll
    for (int c = 0; c < NC; c++) frow[c] = fin + (c * 32 + lane) * PI;

    for (int ci0 = 0; ci0 < CIp; ci0 += 16) {
        __syncthreads();
        for (int e = tid; e < CO * 16; e += 256) {
            int o = e >> 4, g = e & 15;
            int ci = ci0 + g;
            wsm[o * 20 + g] = (ci < CIa) ? __ldg(W + o * CIa + ci) : 0.0f;
        }
        __syncthreads();
        int gmax = (CIp - ci0 < 16) ? (CIp - ci0) : 16;
        for (int g = 0; g < gmax; g += 4) {
            float4 f4[NC];
#pragma unroll
            for (int c = 0; c < NC; c++) f4[c] = *(const float4*)(frow[c] + ci0 + g);
            const float* wb = wsm + obase * 20 + g;
#pragma unroll
            for (int j = 0; j < OB; j++) {
                float4 w4 = *(const float4*)(wb + j * 20);
#pragma unroll
                for (int c = 0; c < NC; c++) {
                    acc[c][j] = fmaf(w4.x, f4[c].x, acc[c][j]);
                    acc[c][j] = fmaf(w4.y, f4[c].y, acc[c][j]);
                    acc[c][j] = fmaf(w4.z, f4[c].z, acc[c][j]);
                    acc[c][j] = fmaf(w4.w, f4[c].w, acc[c][j]);
                }
            }
        }
    }
#pragma unroll
    for (int c = 0; c < NC; c++) {
        float* orow = fo + (c * 32 + lane) * PO + obase;
#pragma unroll
        for (int j = 0; j < OB; j++) orow[j] = fmaxf(acc[c][j], 0.0f);
    }
}

// Last stage: compute, then max over 32 neighbors (lanes) via warp shuffle.
template <int CIa, int CIp, int CO, int PI, int NC>
__device__ __forceinline__ void mlp_last(const float* __restrict__ fin,
                                         float* __restrict__ wsm,
                                         const float* __restrict__ W,
                                         const float* __restrict__ Bv,
                                         float* __restrict__ fout_c0,
                                         float* __restrict__ dout_c0,
                                         int C3sz, int S_, int tid) {
    constexpr int OB = CO / 8;
    int lane = tid & 31;
    int obase = (tid >> 5) * OB;
    float acc[NC][OB];
#pragma unroll
    for (int c = 0; c < NC; c++)
#pragma unroll
        for (int j = 0; j < OB; j++) acc[c][j] = __ldg(Bv + obase + j);
    const float* frow[NC];
#pragma unroll
    for (int c = 0; c < NC; c++) frow[c] = fin + (c * 32 + lane) * PI;

    for (int ci0 = 0; ci0 < CIp; ci0 += 16) {
        __syncthreads();
        for (int e = tid; e < CO * 16; e += 256) {
            int o = e >> 4, g = e & 15;
            int ci = ci0 + g;
            wsm[o * 20 + g] = (ci < CIa) ? __ldg(W + o * CIa + ci) : 0.0f;
        }
        __syncthreads();
        int gmax = (CIp - ci0 < 16) ? (CIp - ci0) : 16;
        for (int g = 0; g < gmax; g += 4) {
            float4 f4[NC];
#pragma unroll
            for (int c = 0; c < NC; c++) f4[c] = *(const float4*)(frow[c] + ci0 + g);
            const float* wb = wsm + obase * 20 + g;
#pragma unroll
            for (int j = 0; j < OB; j++) {
                float4 w4 = *(const float4*)(wb + j * 20);
#pragma unroll
                for (int c = 0; c < NC; c++) {
                    acc[c][j] = fmaf(w4.x, f4[c].x, acc[c][j]);
                    acc[c][j] = fmaf(w4.y, f4[c].y, acc[c][j]);
                    acc[c][j] = fmaf(w4.z, f4[c].z, acc[c][j]);
                    acc[c][j] = fmaf(w4.w, f4[c].w, acc[c][j]);
                }
            }
        }
    }
#pragma unroll
    for (int c = 0; c < NC; c++) {
#pragma unroll
        for (int j = 0; j < OB; j++) {
            float m = fmaxf(acc[c][j], 0.0f);
#pragma unroll
            for (int off = 16; off > 0; off >>= 1)
                m = fmaxf(m, __shfl_xor_sync(FULLMASK, m, off));
            if (lane == 0) {
                int o = obase + j;
                fout_c0[(size_t)c * C3sz + o] = m;
                dout_c0[(size_t)o * S_ + c] = m;
            }
        }
    }
}

// ---------------------------------------------------------------------------
// Fused SA layer, NC centers per block (+ embedded FPS for the NEXT layer in
// the first NBATCH blocks). NWQ = ball-query warps PER CENTER (NC*NWQ <= 8).
// MINB: min blocks/SM (reg cap). MINB=4 only for sa1/sa2 (acc fits 64 regs).
// ---------------------------------------------------------------------------
template <int NP, int S, int D, int C1, int C2, int C3, int CINp, int PA,
          int NWQ, int SOUT, int NC, int MINB>
__global__ __launch_bounds__(256, MINB) void k_sa(const float4* __restrict__ xyz4,
                                                  const float* __restrict__ pts,
                                                  const float4* __restrict__ cxyz,
                                                  const float* __restrict__ W1, const float* __restrict__ B1,
                                                  const float* __restrict__ W2, const float* __restrict__ B2,
                                                  const float* __restrict__ W3, const float* __restrict__ B3,
                                                  float* __restrict__ fout,
                                                  float* __restrict__ dout, float r2,
                                                  float4* __restrict__ nxout,
                                                  float* __restrict__ dout2) {
    constexpr int CIN = D + 3;
    extern __shared__ float smdyn[];
    int bid = blockIdx.x;
    int tid = threadIdx.x;
    if constexpr (SOUT > 0) {
        if (bid < NBATCH) {   // embedded FPS for next layer, scheduled first
            fps_body<S, SOUT, 8, false>(cxyz, nxout, dout2, bid, tid, (float4*)smdyn);
            return;
        }
        bid -= NBATCH;
    }

    float* bufA = smdyn;                 // [NC*32, PA]
    float* bufB = smdyn + NC * 32 * PA;  // [NC*32, PA]
    float* wsm  = smdyn + 2 * NC * 32 * PA;
    __shared__ int hits[8][32];
    __shared__ int cnts[8];
    __shared__ int nidx[NC][32];
    __shared__ float4 cenv[NC];

    constexpr int SG = S / NC;
    int b = bid / SG;
    int s0 = (bid - b * SG) * NC;
    int lane = tid & 31, wd = tid >> 5;

    if (tid < NC) cenv[tid] = __ldg(&cxyz[(size_t)b * S + s0 + tid]);

    // ---- ball query: NC groups of NWQ warps scan disjoint ordered chunks ----
    if (wd < NC * NWQ) {
        int qc = wd / NWQ;
        int qw = wd - qc * NWQ;
        float4 cv = __ldg(&cxyz[(size_t)b * S + s0 + qc]);
        float cx = cv.x, cy = cv.y, cz = cv.z, smc = cv.w;
        constexpr int CHUNK = NP / NWQ;
        const float4* px = xyz4 + (size_t)b * NP;
        int cnt = 0;
        for (int base = qw * CHUNK; base < (qw + 1) * CHUNK; base += 32) {
            int p = base + lane;
            float4 v = __ldg(&px[p]);
            float dot = __fadd_rn(__fadd_rn(__fmul_rn(cx, v.x), __fmul_rn(cy, v.y)),
                                  __fmul_rn(cz, v.z));
            float sq = __fadd_rn(__fadd_rn(smc, v.w), -__fmul_rn(2.0f, dot));
            bool hit = !(sq > r2);
            unsigned m = __ballot_sync(FULLMASK, hit);
            if (hit) {
                int pos = cnt + __popc(m & ((1u << lane) - 1u));
                if (pos < 32) hits[wd][pos] = p;
            }
            cnt += __popc(m);
            if (cnt >= 32) break;
        }
        if (lane == 0) cnts[wd] = (cnt < 32) ? cnt : 32;
    }
    __syncthreads();
    // ---- merge: warp c merges its NWQ chunk lists (ascending index order) ----
    if (wd < NC) {
        int total = 0;
#pragma unroll
        for (int w2 = 0; w2 < NWQ; w2++) {
            int c = cnts[wd * NWQ + w2];
            int take = (c < 32 - total) ? c : (32 - total);
            if (lane < take) nidx[wd][total + lane] = hits[wd * NWQ + w2][lane];
            total += take;
        }
        __syncwarp();
        int i0 = nidx[wd][0];
        if (lane >= total) nidx[wd][lane] = i0;
    }
    __syncthreads();

    // ---- gather: [rel_xyz(3), pts(D), zero-pad] into bufA rows ----
    for (int e = tid; e < NC * 32 * CINp; e += 256) {
        int kk = e / CINp;
        int c = e - kk * CINp;
        int cc = kk >> 5;
        int p = nidx[cc][kk & 31];
        float v = 0.0f;
        if (c < 3) {
            float4 cv = cenv[cc];
            float ccf = (c == 0) ? cv.x : (c == 1) ? cv.y : cv.z;
            const float* xf = (const float*)(xyz4 + (size_t)b * NP + p);
            v = __fadd_rn(xf[c], -ccf);
        } else if (c < CIN) {
            v = pts[((size_t)b * NP + p) * D + (c - 3)];
        }
        bufA[kk * PA + c] = v;
    }
    // (stage-1's leading __syncthreads covers gather completion)

    mlp_mid<CIN, CINp, C1, PA, PA, NC>(bufA, bufB, wsm, W1, B1, tid);
    mlp_mid<C1, C1, C2, PA, PA, NC>(bufB, bufA, wsm, W2, B2, tid);
    mlp_last<C2, C2, C3, PA, NC>(bufA, wsm, W3, B3,
                                 fout + ((size_t)b * S + s0) * C3,
                                 dout + (size_t)b * C3 * S + s0, C3, S, tid);
}

// ---------------------------------------------------------------------------
extern "C" void kernel_launch(void* const* d_in, const int* in_sizes, int n_in,
                              void* d_out, int out_size) {
    const float* xin = (const float*)d_in[0];
    const float* w1a = (const float*)d_in[1];  const float* b1a = (const float*)d_in[2];
    const float* w1b = (const float*)d_in[3];  const float* b1b = (const float*)d_in[4];
    const float* w1c = (const float*)d_in[5];  const float* b1c = (const float*)d_in[6];
    const float* w2a = (const float*)d_in[7];  const float* b2a = (const float*)d_in[8];
    const float* w2b = (const float*)d_in[9];  const float* b2b = (const float*)d_in[10];
    const float* w2c = (const float*)d_in[11]; const float* b2c = (const float*)d_in[12];
    const float* w3a = (const float*)d_in[13]; const float* b3a = (const float*)d_in[14];
    const float* w3b = (const float*)d_in[15]; const float* b3b = (const float*)d_in[16];
    const float* w3c = (const float*)d_in[17]; const float* b3c = (const float*)d_in[18];
    const float* w4a = (const float*)d_in[19]; const float* b4a = (const float*)d_in[20];
    const float* w4b = (const float*)d_in[21]; const float* b4b = (const float*)d_in[22];
    const float* w4c = (const float*)d_in[23]; const float* b4c = (const float*)d_in[24];
    float* out = (float*)d_out;

    float4 *p_xyz0, *p_nx1, *p_nx2, *p_nx3, *p_nx4;
    float *p_pts0, *p_f1, *p_f2, *p_f3, *p_f4;
    cudaGetSymbolAddress((void**)&p_xyz0, g_xyz0);
    cudaGetSymbolAddress((void**)&p_pts0, g_pts0);
    cudaGetSymbolAddress((void**)&p_nx1, g_nx1);
    cudaGetSymbolAddress((void**)&p_f1, g_f1);
    cudaGetSymbolAddress((void**)&p_nx2, g_nx2);
    cudaGetSymbolAddress((void**)&p_f2, g_f2);
    cudaGetSymbolAddress((void**)&p_nx3, g_nx3);
    cudaGetSymbolAddress((void**)&p_f3, g_f3);
    cudaGetSymbolAddress((void**)&p_nx4, g_nx4);
    cudaGetSymbolAddress((void**)&p_f4, g_f4);

    float r2_1 = (float)(0.1 * 0.1);
    float r2_2 = (float)(0.2 * 0.2);
    float r2_3 = (float)(0.4 * 0.4);
    float r2_4 = (float)(0.8 * 0.8);

    // dynamic smem = max(sa: 2*NC*32*PA + COmax*20 floats, fps tail: S*16B)
    const int SMF1 = NPTS0 * 16;                        // 65536 (fps1 float4 mirror)
    const int SM1 = (128 * 36 + 64 * 20) * 4;           // 23552 (fps2 tail: 16384)
    const int SM2 = (128 * 68 + 128 * 20) * 4;          // 45056 (fps3 tail: 4096)
    const int SM3 = (64 * 132 + 256 * 20) * 4;          // 54272 (fps4 tail: 1024)
    const int SM4 = (64 * 260 + 512 * 20) * 4;          // 107520

    cudaFuncSetAttribute(k_front,
                         cudaFuncAttributeMaxDynamicSharedMemorySize, SMF1);
    cudaFuncSetAttribute(k_sa<256, 64, 128, 128, 128, 256, 132, 132, 8, 16, 1, 1>,
                         cudaFuncAttributeMaxDynamicSharedMemorySize, SM3);
    cudaFuncSetAttribute(k_sa<64, 16, 256, 256, 256, 512, 260, 260, 2, 0, 1, 1>,
                         cudaFuncAttributeMaxDynamicSharedMemorySize, SM4);

    // front: fps1 (strided input, blocks 0-15) + transpose (blocks 16-143)
    k_front<<<NBATCH + (NBATCH * NPTS0) / 512, 512, SMF1>>>(
        xin, out + O1, p_nx1, out + O2);

    // layer 1 SA, NC=2, MINB=4 (+ embedded fps2 -> nx2, out O3)
    k_sa<4096, 1024, 9, 32, 32, 64, 12, 36, 4, 256, 2, 4>
        <<<NBATCH * 512 + NBATCH, 256, SM1>>>(
        p_xyz0, p_pts0, p_nx1, w1a, b1a, w1b, b1b, w1c, b1c,
        p_f1, out + O6, r2_1, p_nx2, out + O3);

    // layer 2 SA, NC=2, MINB=4 (+ embedded fps3 -> nx3, out O4)
    k_sa<1024, 256, 64, 64, 64, 128, 68, 68, 4, 64, 2, 4>
        <<<NBATCH * 128 + NBATCH, 256, SM2>>>(
        p_nx1, p_f1, p_nx2, w2a, b2a, w2b, b2b, w2c, b2c,
        p_f2, out + O7, r2_2, p_nx3, out + O4);

    // layer 3 SA, NC=1, MINB=1 (+ embedded fps4 -> nx4, out O5)
    k_sa<256, 64, 128, 128, 128, 256, 132, 132, 8, 16, 1, 1>
        <<<NBATCH * 64 + NBATCH, 256, SM3>>>(
        p_nx2, p_f2, p_nx3, w3a, b3a, w3b, b3b, w3c, b3c,
        p_f3, out + O8, r2_3, p_nx4, out + O5);

    // layer 4 SA, NC=1, MINB=1 (no tail)
    k_sa<64, 16, 256, 256, 256, 512, 260, 260, 2, 0, 1, 1>
        <<<NBATCH * 16, 256, SM4>>>(
        p_nx3, p_f3, p_nx4, w4a, b4a, w4b, b4b, w4c, b4c,
        p_f4, out + O9, r2_4, nullptr, nullptr);
}

// round 15
// speedup vs baseline: 1.0656x; 1.0656x over previous
#include <cuda_runtime.h>

#define NBATCH 16
#define NPTS0  4096
#define FULLMASK 0xffffffffu

// ---------------- device scratch (no allocations allowed) ------------------
__device__ float4 g_xyz0[NBATCH * NPTS0];      // x,y,z,|p|^2
__device__ float  g_pts0[NBATCH * NPTS0 * 9];
__device__ float4 g_nx1[NBATCH * 1024];
__device__ float  g_f1 [NBATCH * 1024 * 64];
__device__ float4 g_nx2[NBATCH * 256];
__device__ float  g_f2 [NBATCH * 256 * 128];
__device__ float4 g_nx3[NBATCH * 64];
__device__ float  g_f3 [NBATCH * 64 * 256];
__device__ float4 g_nx4[NBATCH * 16];
__device__ float  g_f4 [NBATCH * 16 * 512];

// ---------------- d_out offsets (float elements) ----------------------------
#define O1 0        // [16,3,4096]
#define O2 196608   // [16,3,1024]
#define O3 245760   // [16,3,256]
#define O4 258048   // [16,3,64]
#define O5 261120   // [16,3,16]
#define O6 261888   // [16,64,1024]
#define O7 1310464  // [16,128,256]
#define O8 1834752  // [16,256,64]
#define O9 2096896  // [16,512,16]

__device__ __forceinline__ float sq3(float a, float b, float c) {
    return __fadd_rn(__fadd_rn(__fmul_rn(a, a), __fmul_rn(b, b)), __fmul_rn(c, c));
}

// ---- packed f32x2 helpers (lanewise rn == __fadd_rn/__fmul_rn, bit-exact) --
__device__ __forceinline__ unsigned long long pk2(float lo, float hi) {
    unsigned long long r;
    asm("mov.b64 %0, {%1, %2};" : "=l"(r) : "f"(lo), "f"(hi));
    return r;
}
__device__ __forceinline__ void upk2(float& lo, float& hi, unsigned long long v) {
    asm("mov.b64 {%0, %1}, %2;" : "=f"(lo), "=f"(hi) : "l"(v));
}
__device__ __forceinline__ unsigned long long add2(unsigned long long a, unsigned long long b) {
    unsigned long long r;
    asm("add.rn.f32x2 %0, %1, %2;" : "=l"(r) : "l"(a), "l"(b));
    return r;
}
__device__ __forceinline__ unsigned long long mul2(unsigned long long a, unsigned long long b) {
    unsigned long long r;
    asm("mul.rn.f32x2 %0, %1, %2;" : "=l"(r) : "l"(a), "l"(b));
    return r;
}
__device__ __forceinline__ unsigned long long umax64(unsigned long long a, unsigned long long b) {
    return a > b ? a : b;
}

// ---------------------------------------------------------------------------
// FPS body (R12-validated): coords packed 2-wide in REGISTERS (f32x2 math,
// lanewise bit-exact rn; association (dx^2+dy^2)+dz^2 identical to sq3).
// float4 smem mirror for far-point lookup. Strict ">" argmax over ascending
// p == first-max (jnp semantics); cross-warp tie-break via redux.min.
// STRIDED=true: load coords from raw [9,N]-strided input (x=+0,y=+N,z=+2N),
// w computed as sq3 (bit-identical to the transpose path).
// ---------------------------------------------------------------------------
template <int NPf, int Sf, int NW, bool STRIDED>
__device__ void fps_body(const void* __restrict__ srcv, float4* __restrict__ nx,
                         float* __restrict__ dout, int b, int tid, float4* sc4) {
    constexpr int T = NW * 32;
    constexpr int PPT = (NPf + T - 1) / T;
    constexpr bool GUARD = (NPf % T) != 0;
    constexpr int NPAIR = GUARD ? 0 : (PPT / 2);
    __shared__ unsigned long long skey[2][NW];
    int lane = tid & 31, wd = tid >> 5;

    float tx[PPT], ty[PPT], tz[PPT], dist[PPT];
#pragma unroll
    for (int j = 0; j < PPT; j++) {
        int p = tid + j * T;
        dist[j] = 1e10f;
        tx[j] = 0.f; ty[j] = 0.f; tz[j] = 0.f;
        if (!GUARD || p < NPf) {
            float4 v;
            if constexpr (STRIDED) {
                const float* xin = (const float*)srcv + (size_t)b * 9 * NPf;
                float x = xin[p], y = xin[NPf + p], z = xin[2 * NPf + p];
                v = make_float4(x, y, z, sq3(x, y, z));
            } else {
                v = ((const float4*)srcv)[(size_t)b * NPf + p];
            }
            sc4[p] = v;
            tx[j] = v.x; ty[j] = v.y; tz[j] = v.z;
        }
    }
    unsigned long long CX[NPAIR > 0 ? NPAIR : 1];
    unsigned long long CY[NPAIR > 0 ? NPAIR : 1];
    unsigned long long CZ[NPAIR > 0 ? NPAIR : 1];
#pragma unroll
    for (int g = 0; g < NPAIR; g++) {
        CX[g] = pk2(tx[2 * g], tx[2 * g + 1]);
        CY[g] = pk2(ty[2 * g], ty[2 * g + 1]);
        CZ[g] = pk2(tz[2 * g], tz[2 * g + 1]);
    }
    __syncthreads();

    int far = 0;
    for (int s = 0; s < Sf; s++) {
        float4 f = sc4[far];
        if (tid == 0) {
            nx[(size_t)b * Sf + s] = f;
            dout[((size_t)b * 3 + 0) * Sf + s] = f.x;
            dout[((size_t)b * 3 + 1) * Sf + s] = f.y;
            dout[((size_t)b * 3 + 2) * Sf + s] = f.z;
        }
        unsigned bb = 0u, bi = 0xffffffffu;
        unsigned long long nfx = pk2(-f.x, -f.x);
        unsigned long long nfy = pk2(-f.y, -f.y);
        unsigned long long nfz = pk2(-f.z, -f.z);
#pragma unroll
        for (int g = 0; g < NPAIR; g++) {
            unsigned long long dx = add2(CX[g], nfx);
            unsigned long long dy = add2(CY[g], nfy);
            unsigned long long dz = add2(CZ[g], nfz);
            unsigned long long ss = add2(add2(mul2(dx, dx), mul2(dy, dy)), mul2(dz, dz));
            float d0, d1; upk2(d0, d1, ss);
            int p0 = tid + (2 * g) * T, p1 = p0 + T;
            float n0 = fminf(dist[2 * g], d0);     dist[2 * g] = n0;
            float n1 = fminf(dist[2 * g + 1], d1); dist[2 * g + 1] = n1;
            unsigned u0 = __float_as_uint(n0), u1 = __float_as_uint(n1);
            if (u0 > bb) { bb = u0; bi = (unsigned)p0; }   // strict > over ascending p
            if (u1 > bb) { bb = u1; bi = (unsigned)p1; }   //  == first-max semantics
        }
#pragma unroll
        for (int j = 2 * NPAIR; j < PPT; j++) {   // scalar remainder (guarded)
            int p = tid + j * T;
            if (!GUARD || p < NPf) {
                float dxs = __fadd_rn(tx[j], -f.x);
                float dys = __fadd_rn(ty[j], -f.y);
                float dzs = __fadd_rn(tz[j], -f.z);
                float d = sq3(dxs, dys, dzs);
                float nd = fminf(dist[j], d);
                dist[j] = nd;
                unsigned ub = __float_as_uint(nd);
                if (ub > bb) { bb = ub; bi = (unsigned)p; }
            }
        }
        unsigned mb = __reduce_max_sync(FULLMASK, bb);
        unsigned cand = (bb == mb) ? bi : 0xffffffffu;
        unsigned mi = __reduce_min_sync(FULLMASK, cand);
        if (lane == 0)
            skey[s & 1][wd] = ((unsigned long long)mb << 32) |
                              (unsigned long long)(0xffffffffu - mi);
        __syncthreads();
        unsigned long long kk[NW];
#pragma unroll
        for (int i = 0; i < NW; i++) kk[i] = skey[s & 1][i];
#pragma unroll
        for (int st = NW / 2; st > 0; st >>= 1)
#pragma unroll
            for (int i = 0; i < st; i++) kk[i] = umax64(kk[i], kk[i + st]);
        far = (int)(0xffffffffu - (unsigned)(kk[0] & 0xffffffffu));
    }
}

// ---------------------------------------------------------------------------
// Fused transpose + fps1: blocks [0,16) run fps1 reading the RAW strided
// input (no dependence on the transpose); blocks [16,...) transpose
// [B,9,N] -> point-major scratch (+ |p|^2) and emit output region 1.
// ---------------------------------------------------------------------------
__global__ __launch_bounds__(512) void k_front(const float* __restrict__ in,
                                               float* __restrict__ out1,
                                               float4* __restrict__ nx1,
                                               float* __restrict__ dout2) {
    extern __shared__ float smdyn[];
    int bid = blockIdx.x;
    if (bid < NBATCH) {
        fps_body<4096, 1024, 16, true>(in, nx1, dout2, bid, threadIdx.x,
                                       (float4*)smdyn);
        return;
    }
    int i = (bid - NBATCH) * 512 + threadIdx.x;
    if (i >= NBATCH * NPTS0) return;
    int b = i >> 12;
    int n = i & (NPTS0 - 1);
    const float* src = in + (size_t)b * 9 * NPTS0;
    float v[9];
#pragma unroll
    for (int c = 0; c < 9; c++) v[c] = src[c * NPTS0 + n];
#pragma unroll
    for (int c = 0; c < 9; c++) g_pts0[(size_t)i * 9 + c] = v[c];
    g_xyz0[i] = make_float4(v[0], v[1], v[2], sq3(v[0], v[1], v[2]));
#pragma unroll
    for (int c = 0; c < 3; c++) out1[((size_t)b * 3 + c) * NPTS0 + n] = v[c];
}

// ---------------------------------------------------------------------------
// MLP stage (middle), NC centers register-blocked; OB = CO/8 outputs/thread.
// Weights staged in smem chunks of 16 ci-cols (pitch 20). (R12-frozen.)
// ---------------------------------------------------------------------------
template <int CIa, int CIp, int CO, int PI, int PO, int NC>
__device__ __forceinline__ void mlp_mid(const float* __restrict__ fin,
                                        float* __restrict__ fo,
                                        float* __restrict__ wsm,
                                        const float* __restrict__ W,
                                        const float* __restrict__ Bv, int tid) {
    constexpr int OB = CO / 8;
    int lane = tid & 31;
    int obase = (tid >> 5) * OB;
    float acc[NC][OB];
#pragma unroll
    for (int c = 0; c < NC; c++)
#pragma unroll
        for (int j = 0; j < OB; j++) acc[c][j] = __ldg(Bv + obase + j);
    const float* frow[NC];
#pragma unroll
    for (int c = 0; c < NC; c++) frow[c] = fin + (c * 32 + lane) * PI;

    for (int ci0 = 0; ci0 < CIp; ci0 += 16) {
        __syncthreads();
        for (int e = tid; e < CO * 16; e += 256) {
            int o = e >> 4, g = e & 15;
            int ci = ci0 + g;
            wsm[o * 20 + g] = (ci < CIa) ? __ldg(W + o * CIa + ci) : 0.0f;
        }
        __syncthreads();
        int gmax = (CIp - ci0 < 16) ? (CIp - ci0) : 16;
        for (int g = 0; g < gmax; g += 4) {
            float4 f4[NC];
#pragma unroll
            for (int c = 0; c < NC; c++) f4[c] = *(const float4*)(frow[c] + ci0 + g);
            const float* wb = wsm + obase * 20 + g;
#pragma unroll
            for (int j = 0; j < OB; j++) {
                float4 w4 = *(const float4*)(wb + j * 20);
#pragma unroll
                for (int c = 0; c < NC; c++) {
                    acc[c][j] = fmaf(w4.x, f4[c].x, acc[c][j]);
                    acc[c][j] = fmaf(w4.y, f4[c].y, acc[c][j]);
                    acc[c][j] = fmaf(w4.z, f4[c].z, acc[c][j]);
                    acc[c][j] = fmaf(w4.w, f4[c].w, acc[c][j]);
                }
            }
        }
    }
#pragma unroll
    for (int c = 0; c < NC; c++) {
        float* orow = fo + (c * 32 + lane) * PO + obase;
#pragma unroll
        for (int j = 0; j < OB; j++) orow[j] = fmaxf(acc[c][j], 0.0f);
    }
}

// Last stage: compute, then max over 32 neighbors (lanes) via warp shuffle.
template <int CIa, int CIp, int CO, int PI, int NC>
__device__ __forceinline__ void mlp_last(const float* __restrict__ fin,
                                         float* __restrict__ wsm,
                                         const float* __restrict__ W,
                                         const float* __restrict__ Bv,
                                         float* __restrict__ fout_c0,
                                         float* __restrict__ dout_c0,
                                         int C3sz, int S_, int tid) {
    constexpr int OB = CO / 8;
    int lane = tid & 31;
    int obase = (tid >> 5) * OB;
    float acc[NC][OB];
#pragma unroll
    for (int c = 0; c < NC; c++)
#pragma unroll
        for (int j = 0; j < OB; j++) acc[c][j] = __ldg(Bv + obase + j);
    const float* frow[NC];
#pragma unroll
    for (int c = 0; c < NC; c++) frow[c] = fin + (c * 32 + lane) * PI;

    for (int ci0 = 0; ci0 < CIp; ci0 += 16) {
        __syncthreads();
        for (int e = tid; e < CO * 16; e += 256) {
            int o = e >> 4, g = e & 15;
            int ci = ci0 + g;
            wsm[o * 20 + g] = (ci < CIa) ? __ldg(W + o * CIa + ci) : 0.0f;
        }
        __syncthreads();
        int gmax = (CIp - ci0 < 16) ? (CIp - ci0) : 16;
        for (int g = 0; g < gmax; g += 4) {
            float4 f4[NC];
#pragma unroll
            for (int c = 0; c < NC; c++) f4[c] = *(const float4*)(frow[c] + ci0 + g);
            const float* wb = wsm + obase * 20 + g;
#pragma unroll
            for (int j = 0; j < OB; j++) {
                float4 w4 = *(const float4*)(wb + j * 20);
#pragma unroll
                for (int c = 0; c < NC; c++) {
                    acc[c][j] = fmaf(w4.x, f4[c].x, acc[c][j]);
                    acc[c][j] = fmaf(w4.y, f4[c].y, acc[c][j]);
                    acc[c][j] = fmaf(w4.z, f4[c].z, acc[c][j]);
                    acc[c][j] = fmaf(w4.w, f4[c].w, acc[c][j]);
                }
            }
        }
    }
#pragma unroll
    for (int c = 0; c < NC; c++) {
#pragma unroll
        for (int j = 0; j < OB; j++) {
            float m = fmaxf(acc[c][j], 0.0f);
#pragma unroll
            for (int off = 16; off > 0; off >>= 1)
                m = fmaxf(m, __shfl_xor_sync(FULLMASK, m, off));
            if (lane == 0) {
                int o = obase + j;
                fout_c0[(size_t)c * C3sz + o] = m;
                dout_c0[(size_t)o * S_ + c] = m;
            }
        }
    }
}

// ---------------------------------------------------------------------------
// Fused SA layer, NC centers per block (+ embedded FPS for the NEXT layer in
// the first NBATCH blocks). NWQ = ball-query warps PER CENTER (NC*NWQ <= 8).
// (R12-frozen shapes; plain launch bounds, no reg caps.)
// ---------------------------------------------------------------------------
template <int NP, int S, int D, int C1, int C2, int C3, int CINp, int PA,
          int NWQ, int SOUT, int NC>
__global__ __launch_bounds__(256) void k_sa(const float4* __restrict__ xyz4,
                                            const float* __restrict__ pts,
                                            const float4* __restrict__ cxyz,
                                            const float* __restrict__ W1, const float* __restrict__ B1,
                                            const float* __restrict__ W2, const float* __restrict__ B2,
                                            const float* __restrict__ W3, const float* __restrict__ B3,
                                            float* __restrict__ fout,
                                            float* __restrict__ dout, float r2,
                                            float4* __restrict__ nxout,
                                            float* __restrict__ dout2) {
    constexpr int CIN = D + 3;
    extern __shared__ float smdyn[];
    int bid = blockIdx.x;
    int tid = threadIdx.x;
    if constexpr (SOUT > 0) {
        if (bid < NBATCH) {   // embedded FPS for next layer, scheduled first
            fps_body<S, SOUT, 8, false>(cxyz, nxout, dout2, bid, tid, (float4*)smdyn);
            return;
        }
        bid -= NBATCH;
    }

    float* bufA = smdyn;                 // [NC*32, PA]
    float* bufB = smdyn + NC * 32 * PA;  // [NC*32, PA]
    float* wsm  = smdyn + 2 * NC * 32 * PA;
    __shared__ int hits[8][32];
    __shared__ int cnts[8];
    __shared__ int nidx[NC][32];
    __shared__ float4 cenv[NC];

    constexpr int SG = S / NC;
    int b = bid / SG;
    int s0 = (bid - b * SG) * NC;
    int lane = tid & 31, wd = tid >> 5;

    if (tid < NC) cenv[tid] = __ldg(&cxyz[(size_t)b * S + s0 + tid]);

    // ---- ball query: NC groups of NWQ warps scan disjoint ordered chunks ----
    if (wd < NC * NWQ) {
        int qc = wd / NWQ;
        int qw = wd - qc * NWQ;
        float4 cv = __ldg(&cxyz[(size_t)b * S + s0 + qc]);
        float cx = cv.x, cy = cv.y, cz = cv.z, smc = cv.w;
        constexpr int CHUNK = NP / NWQ;
        const float4* px = xyz4 + (size_t)b * NP;
        int cnt = 0;
        for (int base = qw * CHUNK; base < (qw + 1) * CHUNK; base += 32) {
            int p = base + lane;
            float4 v = __ldg(&px[p]);
            float dot = __fadd_rn(__fadd_rn(__fmul_rn(cx, v.x), __fmul_rn(cy, v.y)),
                                  __fmul_rn(cz, v.z));
            float sq = __fadd_rn(__fadd_rn(smc, v.w), -__fmul_rn(2.0f, dot));
            bool hit = !(sq > r2);
            unsigned m = __ballot_sync(FULLMASK, hit);
            if (hit) {
                int pos = cnt + __popc(m & ((1u << lane) - 1u));
                if (pos < 32) hits[wd][pos] = p;
            }
            cnt += __popc(m);
            if (cnt >= 32) break;
        }
        if (lane == 0) cnts[wd] = (cnt < 32) ? cnt : 32;
    }
    __syncthreads();
    // ---- merge: warp c merges its NWQ chunk lists (ascending index order) ----
    if (wd < NC) {
        int total = 0;
#pragma unroll
        for (int w2 = 0; w2 < NWQ; w2++) {
            int c = cnts[wd * NWQ + w2];
            int take = (c < 32 - total) ? c : (32 - total);
            if (lane < take) nidx[wd][total + lane] = hits[wd * NWQ + w2][lane];
            total += take;
        }
        __syncwarp();
        int i0 = nidx[wd][0];
        if (lane >= total) nidx[wd][lane] = i0;
    }
    __syncthreads();

    // ---- gather: [rel_xyz(3), pts(D), zero-pad] into bufA rows ----
    for (int e = tid; e < NC * 32 * CINp; e += 256) {
        int kk = e / CINp;
        int c = e - kk * CINp;
        int cc = kk >> 5;
        int p = nidx[cc][kk & 31];
        float v = 0.0f;
        if (c < 3) {
            float4 cv = cenv[cc];
            float ccf = (c == 0) ? cv.x : (c == 1) ? cv.y : cv.z;
            const float* xf = (const float*)(xyz4 + (size_t)b * NP + p);
            v = __fadd_rn(xf[c], -ccf);
        } else if (c < CIN) {
            v = pts[((size_t)b * NP + p) * D + (c - 3)];
        }
        bufA[kk * PA + c] = v;
    }
    // (stage-1's leading __syncthreads covers gather completion)

    mlp_mid<CIN, CINp, C1, PA, PA, NC>(bufA, bufB, wsm, W1, B1, tid);
    mlp_mid<C1, C1, C2, PA, PA, NC>(bufB, bufA, wsm, W2, B2, tid);
    mlp_last<C2, C2, C3, PA, NC>(bufA, wsm, W3, B3,
                                 fout + ((size_t)b * S + s0) * C3,
                                 dout + (size_t)b * C3 * S + s0, C3, S, tid);
}

// ---------------------------------------------------------------------------
extern "C" void kernel_launch(void* const* d_in, const int* in_sizes, int n_in,
                              void* d_out, int out_size) {
    const float* xin = (const float*)d_in[0];
    const float* w1a = (const float*)d_in[1];  const float* b1a = (const float*)d_in[2];
    const float* w1b = (const float*)d_in[3];  const float* b1b = (const float*)d_in[4];
    const float* w1c = (const float*)d_in[5];  const float* b1c = (const float*)d_in[6];
    const float* w2a = (const float*)d_in[7];  const float* b2a = (const float*)d_in[8];
    const float* w2b = (const float*)d_in[9];  const float* b2b = (const float*)d_in[10];
    const float* w2c = (const float*)d_in[11]; const float* b2c = (const float*)d_in[12];
    const float* w3a = (const float*)d_in[13]; const float* b3a = (const float*)d_in[14];
    const float* w3b = (const float*)d_in[15]; const float* b3b = (const float*)d_in[16];
    const float* w3c = (const float*)d_in[17]; const float* b3c = (const float*)d_in[18];
    const float* w4a = (const float*)d_in[19]; const float* b4a = (const float*)d_in[20];
    const float* w4b = (const float*)d_in[21]; const float* b4b = (const float*)d_in[22];
    const float* w4c = (const float*)d_in[23]; const float* b4c = (const float*)d_in[24];
    float* out = (float*)d_out;

    float4 *p_xyz0, *p_nx1, *p_nx2, *p_nx3, *p_nx4;
    float *p_pts0, *p_f1, *p_f2, *p_f3, *p_f4;
    cudaGetSymbolAddress((void**)&p_xyz0, g_xyz0);
    cudaGetSymbolAddress((void**)&p_pts0, g_pts0);
    cudaGetSymbolAddress((void**)&p_nx1, g_nx1);
    cudaGetSymbolAddress((void**)&p_f1, g_f1);
    cudaGetSymbolAddress((void**)&p_nx2, g_nx2);
    cudaGetSymbolAddress((void**)&p_f2, g_f2);
    cudaGetSymbolAddress((void**)&p_nx3, g_nx3);
    cudaGetSymbolAddress((void**)&p_f3, g_f3);
    cudaGetSymbolAddress((void**)&p_nx4, g_nx4);
    cudaGetSymbolAddress((void**)&p_f4, g_f4);

    float r2_1 = (float)(0.1 * 0.1);
    float r2_2 = (float)(0.2 * 0.2);
    float r2_3 = (float)(0.4 * 0.4);
    float r2_4 = (float)(0.8 * 0.8);

    // dynamic smem = max(sa: 2*NC*32*PA + COmax*20 floats, fps tail: S*16B)
    const int SMF1 = NPTS0 * 16;                        // 65536 (fps1 float4 mirror)
    const int SM1 = (128 * 36 + 64 * 20) * 4;           // 23552 (fps2 tail: 16384)
    const int SM2 = (128 * 68 + 128 * 20) * 4;          // 45056 (fps3 tail: 4096)
    const int SM3 = (64 * 132 + 256 * 20) * 4;          // 54272 (fps4 tail: 1024)
    const int SM4 = (64 * 260 + 512 * 20) * 4;          // 107520

    cudaFuncSetAttribute(k_front,
                         cudaFuncAttributeMaxDynamicSharedMemorySize, SMF1);
    cudaFuncSetAttribute(k_sa<256, 64, 128, 128, 128, 256, 132, 132, 8, 16, 1>,
                         cudaFuncAttributeMaxDynamicSharedMemorySize, SM3);
    cudaFuncSetAttribute(k_sa<64, 16, 256, 256, 256, 512, 260, 260, 2, 0, 1>,
                         cudaFuncAttributeMaxDynamicSharedMemorySize, SM4);

    // front: fps1 (strided input, blocks 0-15) + transpose (blocks 16-143)
    k_front<<<NBATCH + (NBATCH * NPTS0) / 512, 512, SMF1>>>(
        xin, out + O1, p_nx1, out + O2);

    // layer 1 SA, NC=2 (+ embedded fps2 -> nx2, out O3)
    k_sa<4096, 1024, 9, 32, 32, 64, 12, 36, 4, 256, 2>
        <<<NBATCH * 512 + NBATCH, 256, SM1>>>(
        p_xyz0, p_pts0, p_nx1, w1a, b1a, w1b, b1b, w1c, b1c,
        p_f1, out + O6, r2_1, p_nx2, out + O3);

    // layer 2 SA, NC=2 (+ embedded fps3 -> nx3, out O4)
    k_sa<1024, 256, 64, 64, 64, 128, 68, 68, 4, 64, 2>
        <<<NBATCH * 128 + NBATCH, 256, SM2>>>(
        p_nx1, p_f1, p_nx2, w2a, b2a, w2b, b2b, w2c, b2c,
        p_f2, out + O7, r2_2, p_nx3, out + O4);

    // layer 3 SA, NC=1 (+ embedded fps4 -> nx4, out O5)
    k_sa<256, 64, 128, 128, 128, 256, 132, 132, 8, 16, 1>
        <<<NBATCH * 64 + NBATCH, 256, SM3>>>(
        p_nx2, p_f2, p_nx3, w3a, b3a, w3b, b3b, w3c, b3c,
        p_f3, out + O8, r2_3, p_nx4, out + O5);

    // layer 4 SA, NC=1 (no tail)
    k_sa<64, 16, 256, 256, 256, 512, 260, 260, 2, 0, 1>
        <<<NBATCH * 16, 256, SM4>>>(
        p_nx3, p_f3, p_nx4, w4a, b4a, w4b, b4b, w4c, b4c,
        p_f4, out + O9, r2_4, nullptr, nullptr);
}

// round 16
// speedup vs baseline: 1.0841x; 1.0174x over previous
#include <cuda_runtime.h>

#define NBATCH 16
#define NPTS0  4096
#define FULLMASK 0xffffffffu

// ---------------- device scratch (no allocations allowed) ------------------
__device__ float4 g_xyz0[NBATCH * NPTS0];      // x,y,z,|p|^2
__device__ float  g_pts0[NBATCH * NPTS0 * 9];
__device__ float4 g_nx1[NBATCH * 1024];
__device__ float  g_f1 [NBATCH * 1024 * 64];
__device__ float4 g_nx2[NBATCH * 256];
__device__ float  g_f2 [NBATCH * 256 * 128];
__device__ float4 g_nx3[NBATCH * 64];
__device__ float  g_f3 [NBATCH * 64 * 256];
__device__ float4 g_nx4[NBATCH * 16];
__device__ float  g_f4 [NBATCH * 16 * 512];

// ---------------- d_out offsets (float elements) ----------------------------
#define O1 0        // [16,3,4096]
#define O2 196608   // [16,3,1024]
#define O3 245760   // [16,3,256]
#define O4 258048   // [16,3,64]
#define O5 261120   // [16,3,16]
#define O6 261888   // [16,64,1024]
#define O7 1310464  // [16,128,256]
#define O8 1834752  // [16,256,64]
#define O9 2096896  // [16,512,16]

__device__ __forceinline__ float sq3(float a, float b, float c) {
    return __fadd_rn(__fadd_rn(__fmul_rn(a, a), __fmul_rn(b, b)), __fmul_rn(c, c));
}

// ---- packed f32x2 helpers (lanewise rn == __fadd_rn/__fmul_rn, bit-exact) --
__device__ __forceinline__ unsigned long long pk2(float lo, float hi) {
    unsigned long long r;
    asm("mov.b64 %0, {%1, %2};" : "=l"(r) : "f"(lo), "f"(hi));
    return r;
}
__device__ __forceinline__ void upk2(float& lo, float& hi, unsigned long long v) {
    asm("mov.b64 {%0, %1}, %2;" : "=f"(lo), "=f"(hi) : "l"(v));
}
__device__ __forceinline__ unsigned long long add2(unsigned long long a, unsigned long long b) {
    unsigned long long r;
    asm("add.rn.f32x2 %0, %1, %2;" : "=l"(r) : "l"(a), "l"(b));
    return r;
}
__device__ __forceinline__ unsigned long long mul2(unsigned long long a, unsigned long long b) {
    unsigned long long r;
    asm("mul.rn.f32x2 %0, %1, %2;" : "=l"(r) : "l"(a), "l"(b));
    return r;
}
__device__ __forceinline__ unsigned long long umax64(unsigned long long a, unsigned long long b) {
    return a > b ? a : b;
}

// ---------------------------------------------------------------------------
// FPS body (R12-validated): coords packed 2-wide in REGISTERS (f32x2 math,
// lanewise bit-exact rn; association (dx^2+dy^2)+dz^2 identical to sq3).
// float4 smem mirror for far-point lookup. Strict ">" argmax over ascending
// p == first-max (jnp semantics); cross-warp tie-break via redux.min.
// STRIDED=true: load coords from raw [9,N]-strided input.
// ---------------------------------------------------------------------------
template <int NPf, int Sf, int NW, bool STRIDED>
__device__ void fps_body(const void* __restrict__ srcv, float4* __restrict__ nx,
                         float* __restrict__ dout, int b, int tid, float4* sc4) {
    constexpr int T = NW * 32;
    constexpr int PPT = (NPf + T - 1) / T;
    constexpr bool GUARD = (NPf % T) != 0;
    constexpr int NPAIR = GUARD ? 0 : (PPT / 2);
    __shared__ unsigned long long skey[2][NW];
    int lane = tid & 31, wd = tid >> 5;

    float tx[PPT], ty[PPT], tz[PPT], dist[PPT];
#pragma unroll
    for (int j = 0; j < PPT; j++) {
        int p = tid + j * T;
        dist[j] = 1e10f;
        tx[j] = 0.f; ty[j] = 0.f; tz[j] = 0.f;
        if (!GUARD || p < NPf) {
            float4 v;
            if constexpr (STRIDED) {
                const float* xin = (const float*)srcv + (size_t)b * 9 * NPf;
                float x = xin[p], y = xin[NPf + p], z = xin[2 * NPf + p];
                v = make_float4(x, y, z, sq3(x, y, z));
            } else {
                v = ((const float4*)srcv)[(size_t)b * NPf + p];
            }
            sc4[p] = v;
            tx[j] = v.x; ty[j] = v.y; tz[j] = v.z;
        }
    }
    unsigned long long CX[NPAIR > 0 ? NPAIR : 1];
    unsigned long long CY[NPAIR > 0 ? NPAIR : 1];
    unsigned long long CZ[NPAIR > 0 ? NPAIR : 1];
#pragma unroll
    for (int g = 0; g < NPAIR; g++) {
        CX[g] = pk2(tx[2 * g], tx[2 * g + 1]);
        CY[g] = pk2(ty[2 * g], ty[2 * g + 1]);
        CZ[g] = pk2(tz[2 * g], tz[2 * g + 1]);
    }
    __syncthreads();

    int far = 0;
    for (int s = 0; s < Sf; s++) {
        float4 f = sc4[far];
        if (tid == 0) {
            nx[(size_t)b * Sf + s] = f;
            dout[((size_t)b * 3 + 0) * Sf + s] = f.x;
            dout[((size_t)b * 3 + 1) * Sf + s] = f.y;
            dout[((size_t)b * 3 + 2) * Sf + s] = f.z;
        }
        unsigned bb = 0u, bi = 0xffffffffu;
        unsigned long long nfx = pk2(-f.x, -f.x);
        unsigned long long nfy = pk2(-f.y, -f.y);
        unsigned long long nfz = pk2(-f.z, -f.z);
#pragma unroll
        for (int g = 0; g < NPAIR; g++) {
            unsigned long long dx = add2(CX[g], nfx);
            unsigned long long dy = add2(CY[g], nfy);
            unsigned long long dz = add2(CZ[g], nfz);
            unsigned long long ss = add2(add2(mul2(dx, dx), mul2(dy, dy)), mul2(dz, dz));
            float d0, d1; upk2(d0, d1, ss);
            int p0 = tid + (2 * g) * T, p1 = p0 + T;
            float n0 = fminf(dist[2 * g], d0);     dist[2 * g] = n0;
            float n1 = fminf(dist[2 * g + 1], d1); dist[2 * g + 1] = n1;
            unsigned u0 = __float_as_uint(n0), u1 = __float_as_uint(n1);
            if (u0 > bb) { bb = u0; bi = (unsigned)p0; }   // strict > over ascending p
            if (u1 > bb) { bb = u1; bi = (unsigned)p1; }   //  == first-max semantics
        }
#pragma unroll
        for (int j = 2 * NPAIR; j < PPT; j++) {   // scalar remainder (guarded)
            int p = tid + j * T;
            if (!GUARD || p < NPf) {
                float dxs = __fadd_rn(tx[j], -f.x);
                float dys = __fadd_rn(ty[j], -f.y);
                float dzs = __fadd_rn(tz[j], -f.z);
                float d = sq3(dxs, dys, dzs);
                float nd = fminf(dist[j], d);
                dist[j] = nd;
                unsigned ub = __float_as_uint(nd);
                if (ub > bb) { bb = ub; bi = (unsigned)p; }
            }
        }
        unsigned mb = __reduce_max_sync(FULLMASK, bb);
        unsigned cand = (bb == mb) ? bi : 0xffffffffu;
        unsigned mi = __reduce_min_sync(FULLMASK, cand);
        if (lane == 0)
            skey[s & 1][wd] = ((unsigned long long)mb << 32) |
                              (unsigned long long)(0xffffffffu - mi);
        __syncthreads();
        unsigned long long kk[NW];
#pragma unroll
        for (int i = 0; i < NW; i++) kk[i] = skey[s & 1][i];
#pragma unroll
        for (int st = NW / 2; st > 0; st >>= 1)
#pragma unroll
            for (int i = 0; i < st; i++) kk[i] = umax64(kk[i], kk[i + st]);
        far = (int)(0xffffffffu - (unsigned)(kk[0] & 0xffffffffu));
    }
}

// ---------------------------------------------------------------------------
// Fused transpose + fps1 (R15-validated).
// ---------------------------------------------------------------------------
__global__ __launch_bounds__(512) void k_front(const float* __restrict__ in,
                                               float* __restrict__ out1,
                                               float4* __restrict__ nx1,
                                               float* __restrict__ dout2) {
    extern __shared__ float smdyn[];
    int bid = blockIdx.x;
    if (bid < NBATCH) {
        fps_body<4096, 1024, 16, true>(in, nx1, dout2, bid, threadIdx.x,
                                       (float4*)smdyn);
        return;
    }
    int i = (bid - NBATCH) * 512 + threadIdx.x;
    if (i >= NBATCH * NPTS0) return;
    int b = i >> 12;
    int n = i & (NPTS0 - 1);
    const float* src = in + (size_t)b * 9 * NPTS0;
    float v[9];
#pragma unroll
    for (int c = 0; c < 9; c++) v[c] = src[c * NPTS0 + n];
#pragma unroll
    for (int c = 0; c < 9; c++) g_pts0[(size_t)i * 9 + c] = v[c];
    g_xyz0[i] = make_float4(v[0], v[1], v[2], sq3(v[0], v[1], v[2]));
#pragma unroll
    for (int c = 0; c < 3; c++) out1[((size_t)b * 3 + c) * NPTS0 + n] = v[c];
}

// ---------------------------------------------------------------------------
// MLP stage (middle), NC centers register-blocked; WCH = weight-chunk width
// (16 or 32; pitch WCH+4). WCH=32 halves the barrier count per stage.
// ---------------------------------------------------------------------------
template <int CIa, int CIp, int CO, int PI, int PO, int NC, int WCH>
__device__ __forceinline__ void mlp_mid(const float* __restrict__ fin,
                                        float* __restrict__ fo,
                                        float* __restrict__ wsm,
                                        const float* __restrict__ W,
                                        const float* __restrict__ Bv, int tid) {
    constexpr int OB = CO / 8;
    constexpr int WP = WCH + 4;
    int lane = tid & 31;
    int obase = (tid >> 5) * OB;
    float acc[NC][OB];
#pragma unroll
    for (int c = 0; c < NC; c++)
#pragma unroll
        for (int j = 0; j < OB; j++) acc[c][j] = __ldg(Bv + obase + j);
    const float* frow[NC];
#pragma unroll
    for (int c = 0; c < NC; c++) frow[c] = fin + (c * 32 + lane) * PI;

    for (int ci0 = 0; ci0 < CIp; ci0 += WCH) {
        __syncthreads();
        for (int e = tid; e < CO * WCH; e += 256) {
            int o = e / WCH, g = e - o * WCH;
            int ci = ci0 + g;
            wsm[o * WP + g] = (ci < CIa) ? __ldg(W + o * CIa + ci) : 0.0f;
        }
        __syncthreads();
        int gmax = (CIp - ci0 < WCH) ? (CIp - ci0) : WCH;
        for (int g = 0; g < gmax; g += 4) {
            float4 f4[NC];
#pragma unroll
            for (int c = 0; c < NC; c++) f4[c] = *(const float4*)(frow[c] + ci0 + g);
            const float* wb = wsm + obase * WP + g;
#pragma unroll
            for (int j = 0; j < OB; j++) {
                float4 w4 = *(const float4*)(wb + j * WP);
#pragma unroll
                for (int c = 0; c < NC; c++) {
                    acc[c][j] = fmaf(w4.x, f4[c].x, acc[c][j]);
                    acc[c][j] = fmaf(w4.y, f4[c].y, acc[c][j]);
                    acc[c][j] = fmaf(w4.z, f4[c].z, acc[c][j]);
                    acc[c][j] = fmaf(w4.w, f4[c].w, acc[c][j]);
                }
            }
        }
    }
#pragma unroll
    for (int c = 0; c < NC; c++) {
        float* orow = fo + (c * 32 + lane) * PO + obase;
#pragma unroll
        for (int j = 0; j < OB; j++) orow[j] = fmaxf(acc[c][j], 0.0f);
    }
}

// Last stage: compute, then max over 32 neighbors (lanes) via warp shuffle.
template <int CIa, int CIp, int CO, int PI, int NC, int WCH>
__device__ __forceinline__ void mlp_last(const float* __restrict__ fin,
                                         float* __restrict__ wsm,
                                         const float* __restrict__ W,
                                         const float* __restrict__ Bv,
                                         float* __restrict__ fout_c0,
                                         float* __restrict__ dout_c0,
                                         int C3sz, int S_, int tid) {
    constexpr int OB = CO / 8;
    constexpr int WP = WCH + 4;
    int lane = tid & 31;
    int obase = (tid >> 5) * OB;
    float acc[NC][OB];
#pragma unroll
    for (int c = 0; c < NC; c++)
#pragma unroll
        for (int j = 0; j < OB; j++) acc[c][j] = __ldg(Bv + obase + j);
    const float* frow[NC];
#pragma unroll
    for (int c = 0; c < NC; c++) frow[c] = fin + (c * 32 + lane) * PI;

    for (int ci0 = 0; ci0 < CIp; ci0 += WCH) {
        __syncthreads();
        for (int e = tid; e < CO * WCH; e += 256) {
            int o = e / WCH, g = e - o * WCH;
            int ci = ci0 + g;
            wsm[o * WP + g] = (ci < CIa) ? __ldg(W + o * CIa + ci) : 0.0f;
        }
        __syncthreads();
        int gmax = (CIp - ci0 < WCH) ? (CIp - ci0) : WCH;
        for (int g = 0; g < gmax; g += 4) {
            float4 f4[NC];
#pragma unroll
            for (int c = 0; c < NC; c++) f4[c] = *(const float4*)(frow[c] + ci0 + g);
            const float* wb = wsm + obase * WP + g;
#pragma unroll
            for (int j = 0; j < OB; j++) {
                float4 w4 = *(const float4*)(wb + j * WP);
#pragma unroll
                for (int c = 0; c < NC; c++) {
                    acc[c][j] = fmaf(w4.x, f4[c].x, acc[c][j]);
                    acc[c][j] = fmaf(w4.y, f4[c].y, acc[c][j]);
                    acc[c][j] = fmaf(w4.z, f4[c].z, acc[c][j]);
                    acc[c][j] = fmaf(w4.w, f4[c].w, acc[c][j]);
                }
            }
        }
    }
#pragma unroll
    for (int c = 0; c < NC; c++) {
#pragma unroll
        for (int j = 0; j < OB; j++) {
            float m = fmaxf(acc[c][j], 0.0f);
#pragma unroll
            for (int off = 16; off > 0; off >>= 1)
                m = fmaxf(m, __shfl_xor_sync(FULLMASK, m, off));
            if (lane == 0) {
                int o = obase + j;
                fout_c0[(size_t)c * C3sz + o] = m;
                dout_c0[(size_t)o * S_ + c] = m;
            }
        }
    }
}

// ---------------------------------------------------------------------------
// Fused SA layer, NC centers per block (+ embedded FPS for the NEXT layer in
// the first NBATCH blocks). NWQ = ball-query warps PER CENTER (NC*NWQ <= 8).
// ---------------------------------------------------------------------------
template <int NP, int S, int D, int C1, int C2, int C3, int CINp, int PA,
          int NWQ, int SOUT, int NC, int WCH>
__global__ __launch_bounds__(256) void k_sa(const float4* __restrict__ xyz4,
                                            const float* __restrict__ pts,
                                            const float4* __restrict__ cxyz,
                                            const float* __restrict__ W1, const float* __restrict__ B1,
                                            const float* __restrict__ W2, const float* __restrict__ B2,
                                            const float* __restrict__ W3, const float* __restrict__ B3,
                                            float* __restrict__ fout,
                                            float* __restrict__ dout, float r2,
                                            float4* __restrict__ nxout,
                                            float* __restrict__ dout2) {
    constexpr int CIN = D + 3;
    extern __shared__ float smdyn[];
    int bid = blockIdx.x;
    int tid = threadIdx.x;
    if constexpr (SOUT > 0) {
        if (bid < NBATCH) {   // embedded FPS for next layer, scheduled first
            fps_body<S, SOUT, 8, false>(cxyz, nxout, dout2, bid, tid, (float4*)smdyn);
            return;
        }
        bid -= NBATCH;
    }

    float* bufA = smdyn;                 // [NC*32, PA]
    float* bufB = smdyn + NC * 32 * PA;  // [NC*32, PA]
    float* wsm  = smdyn + 2 * NC * 32 * PA;
    __shared__ int hits[8][32];
    __shared__ int cnts[8];
    __shared__ int nidx[NC][32];
    __shared__ float4 cenv[NC];

    constexpr int SG = S / NC;
    int b = bid / SG;
    int s0 = (bid - b * SG) * NC;
    int lane = tid & 31, wd = tid >> 5;

    if (tid < NC) cenv[tid] = __ldg(&cxyz[(size_t)b * S + s0 + tid]);

    // ---- ball query: NC groups of NWQ warps scan disjoint ordered chunks ----
    if (wd < NC * NWQ) {
        int qc = wd / NWQ;
        int qw = wd - qc * NWQ;
        float4 cv = __ldg(&cxyz[(size_t)b * S + s0 + qc]);
        float cx = cv.x, cy = cv.y, cz = cv.z, smc = cv.w;
        constexpr int CHUNK = NP / NWQ;
        const float4* px = xyz4 + (size_t)b * NP;
        int cnt = 0;
        for (int base = qw * CHUNK; base < (qw + 1) * CHUNK; base += 32) {
            int p = base + lane;
            float4 v = __ldg(&px[p]);
            float dot = __fadd_rn(__fadd_rn(__fmul_rn(cx, v.x), __fmul_rn(cy, v.y)),
                                  __fmul_rn(cz, v.z));
            float sq = __fadd_rn(__fadd_rn(smc, v.w), -__fmul_rn(2.0f, dot));
            bool hit = !(sq > r2);
            unsigned m = __ballot_sync(FULLMASK, hit);
            if (hit) {
                int pos = cnt + __popc(m & ((1u << lane) - 1u));
                if (pos < 32) hits[wd][pos] = p;
            }
            cnt += __popc(m);
            if (cnt >= 32) break;
        }
        if (lane == 0) cnts[wd] = (cnt < 32) ? cnt : 32;
    }
    __syncthreads();
    // ---- merge: warp c merges its NWQ chunk lists (ascending index order) ----
    if (wd < NC) {
        int total = 0;
#pragma unroll
        for (int w2 = 0; w2 < NWQ; w2++) {
            int c = cnts[wd * NWQ + w2];
            int take = (c < 32 - total) ? c : (32 - total);
            if (lane < take) nidx[wd][total + lane] = hits[wd * NWQ + w2][lane];
            total += take;
        }
        __syncwarp();
        int i0 = nidx[wd][0];
        if (lane >= total) nidx[wd][lane] = i0;
    }
    __syncthreads();

    // ---- gather: [rel_xyz(3), pts(D), zero-pad] into bufA rows ----
    for (int e = tid; e < NC * 32 * CINp; e += 256) {
        int kk = e / CINp;
        int c = e - kk * CINp;
        int cc = kk >> 5;
        int p = nidx[cc][kk & 31];
        float v = 0.0f;
        if (c < 3) {
            float4 cv = cenv[cc];
            float ccf = (c == 0) ? cv.x : (c == 1) ? cv.y : cv.z;
            const float* xf = (const float*)(xyz4 + (size_t)b * NP + p);
            v = __fadd_rn(xf[c], -ccf);
        } else if (c < CIN) {
            v = pts[((size_t)b * NP + p) * D + (c - 3)];
        }
        bufA[kk * PA + c] = v;
    }
    // (stage-1's leading __syncthreads covers gather completion)

    mlp_mid<CIN, CINp, C1, PA, PA, NC, WCH>(bufA, bufB, wsm, W1, B1, tid);
    mlp_mid<C1, C1, C2, PA, PA, NC, WCH>(bufB, bufA, wsm, W2, B2, tid);
    mlp_last<C2, C2, C3, PA, NC, WCH>(bufA, wsm, W3, B3,
                                      fout + ((size_t)b * S + s0) * C3,
                                      dout + (size_t)b * C3 * S + s0, C3, S, tid);
}

// ---------------------------------------------------------------------------
extern "C" void kernel_launch(void* const* d_in, const int* in_sizes, int n_in,
                              void* d_out, int out_size) {
    const float* xin = (const float*)d_in[0];
    const float* w1a = (const float*)d_in[1];  const float* b1a = (const float*)d_in[2];
    const float* w1b = (const float*)d_in[3];  const float* b1b = (const float*)d_in[4];
    const float* w1c = (const float*)d_in[5];  const float* b1c = (const float*)d_in[6];
    const float* w2a = (const float*)d_in[7];  const float* b2a = (const float*)d_in[8];
    const float* w2b = (const float*)d_in[9];  const float* b2b = (const float*)d_in[10];
    const float* w2c = (const float*)d_in[11]; const float* b2c = (const float*)d_in[12];
    const float* w3a = (const float*)d_in[13]; const float* b3a = (const float*)d_in[14];
    const float* w3b = (const float*)d_in[15]; const float* b3b = (const float*)d_in[16];
    const float* w3c = (const float*)d_in[17]; const float* b3c = (const float*)d_in[18];
    const float* w4a = (const float*)d_in[19]; const float* b4a = (const float*)d_in[20];
    const float* w4b = (const float*)d_in[21]; const float* b4b = (const float*)d_in[22];
    const float* w4c = (const float*)d_in[23]; const float* b4c = (const float*)d_in[24];
    float* out = (float*)d_out;

    float4 *p_xyz0, *p_nx1, *p_nx2, *p_nx3, *p_nx4;
    float *p_pts0, *p_f1, *p_f2, *p_f3, *p_f4;
    cudaGetSymbolAddress((void**)&p_xyz0, g_xyz0);
    cudaGetSymbolAddress((void**)&p_pts0, g_pts0);
    cudaGetSymbolAddress((void**)&p_nx1, g_nx1);
    cudaGetSymbolAddress((void**)&p_f1, g_f1);
    cudaGetSymbolAddress((void**)&p_nx2, g_nx2);
    cudaGetSymbolAddress((void**)&p_f2, g_f2);
    cudaGetSymbolAddress((void**)&p_nx3, g_nx3);
    cudaGetSymbolAddress((void**)&p_f3, g_f3);
    cudaGetSymbolAddress((void**)&p_nx4, g_nx4);
    cudaGetSymbolAddress((void**)&p_f4, g_f4);

    float r2_1 = (float)(0.1 * 0.1);
    float r2_2 = (float)(0.2 * 0.2);
    float r2_3 = (float)(0.4 * 0.4);
    float r2_4 = (float)(0.8 * 0.8);

    // dynamic smem = max(sa: 2*NC*32*PA + COmax*(WCH+4) floats, fps tail S*16B)
    const int SMF1 = NPTS0 * 16;                        // 65536
    const int SM1 = (128 * 36 + 64 * 36) * 4;           // 27648 (fps2 tail: 16384)
    const int SM2 = (128 * 68 + 128 * 36) * 4;          // 53248 (fps3 tail: 4096)
    const int SM3 = (64 * 132 + 256 * 36) * 4;          // 70656 (fps4 tail: 1024)
    const int SM4 = (64 * 260 + 512 * 20) * 4;          // 107520 (WCH=16)

    cudaFuncSetAttribute(k_front,
                         cudaFuncAttributeMaxDynamicSharedMemorySize, SMF1);
    cudaFuncSetAttribute(k_sa<1024, 256, 64, 64, 64, 128, 68, 68, 4, 64, 2, 32>,
                         cudaFuncAttributeMaxDynamicSharedMemorySize, SM2);
    cudaFuncSetAttribute(k_sa<256, 64, 128, 128, 128, 256, 132, 132, 8, 16, 1, 32>,
                         cudaFuncAttributeMaxDynamicSharedMemorySize, SM3);
    cudaFuncSetAttribute(k_sa<64, 16, 256, 256, 256, 512, 260, 260, 2, 0, 1, 16>,
                         cudaFuncAttributeMaxDynamicSharedMemorySize, SM4);

    // front: fps1 (strided input, blocks 0-15) + transpose (blocks 16-143)
    k_front<<<NBATCH + (NBATCH * NPTS0) / 512, 512, SMF1>>>(
        xin, out + O1, p_nx1, out + O2);

    // layer 1 SA, NC=2, WCH=32 (+ embedded fps2 -> nx2, out O3)
    k_sa<4096, 1024, 9, 32, 32, 64, 12, 36, 4, 256, 2, 32>
        <<<NBATCH * 512 + NBATCH, 256, SM1>>>(
        p_xyz0, p_pts0, p_nx1, w1a, b1a, w1b, b1b, w1c, b1c,
        p_f1, out + O6, r2_1, p_nx2, out + O3);

    // layer 2 SA, NC=2, WCH=32 (+ embedded fps3 -> nx3, out O4)
    k_sa<1024, 256, 64, 64, 64, 128, 68, 68, 4, 64, 2, 32>
        <<<NBATCH * 128 + NBATCH, 256, SM2>>>(
        p_nx1, p_f1, p_nx2, w2a, b2a, w2b, b2b, w2c, b2c,
        p_f2, out + O7, r2_2, p_nx3, out + O4);

    // layer 3 SA, NC=1, WCH=32 (+ embedded fps4 -> nx4, out O5)
    k_sa<256, 64, 128, 128, 128, 256, 132, 132, 8, 16, 1, 32>
        <<<NBATCH * 64 + NBATCH, 256, SM3>>>(
        p_nx2, p_f2, p_nx3, w3a, b3a, w3b, b3b, w3c, b3c,
        p_f3, out + O8, r2_3, p_nx4, out + O5);

    // layer 4 SA, NC=1, WCH=16 (no tail; smem keeps 2 blocks/SM)
    k_sa<64, 16, 256, 256, 256, 512, 260, 260, 2, 0, 1, 16>
        <<<NBATCH * 16, 256, SM4>>>(
        p_nx3, p_f3, p_nx4, w4a, b4a, w4b, b4b, w4c, b4c,
        p_f4, out + O9, r2_4, nullptr, nullptr);
}